// round 3
// baseline (speedup 1.0000x reference)
#include <cuda_runtime.h>
#include <cstdint>
#include <cstddef>

// Problem constants
constexpr int SEQ   = 1024;
constexpr int HIDC  = 1024;
constexpr int NHC   = 32;
constexpr int HDC   = 32;
constexpr int BATCH = 4;
constexpr int MR    = BATCH * SEQ;   // 4096 rows

// Scratch (static __device__ arrays: allowed; no runtime allocation)
__device__ float g_q[(size_t)MR * HIDC];
__device__ float g_k[(size_t)MR * HIDC];
__device__ float g_v[(size_t)MR * HIDC];
__device__ float g_ctx[(size_t)MR * HIDC];
__device__ float g_x[(size_t)MR * HIDC];

// ---------------------------------------------------------------------------
// SGEMM: C[m][n] = sum_k A[m][k] * B[n][k] + bias[n] (+ resid[m][n])
// A: (4096 x 1024) row-major, B: (1024 x 1024) row-major (torch Linear weight)
// BM=128, BN=128, BK=8, 256 threads, 8x8 micro-tile.
// ---------------------------------------------------------------------------
__device__ __forceinline__ void gemm_body(const float* __restrict__ A,
                                          const float* __restrict__ B,
                                          const float* __restrict__ bias,
                                          const float* __restrict__ resid,
                                          float* __restrict__ C)
{
    __shared__ float As[8][128];
    __shared__ float Bs[8][128];
    const int t  = threadIdx.x;
    const int m0 = blockIdx.y * 128;
    const int n0 = blockIdx.x * 128;
    const int lrow = t >> 1;           // 0..127
    const int lcol = (t & 1) * 4;      // 0 or 4
    const float* Ap = A + (size_t)(m0 + lrow) * HIDC + lcol;
    const float* Bp = B + (size_t)(n0 + lrow) * HIDC + lcol;
    const int tx = t & 15;
    const int ty = t >> 4;

    float acc[8][8];
#pragma unroll
    for (int i = 0; i < 8; i++)
#pragma unroll
        for (int j = 0; j < 8; j++) acc[i][j] = 0.f;

    float4 a_pre = *(const float4*)Ap;
    float4 b_pre = *(const float4*)Bp;

    for (int kt = 0; kt < HIDC / 8; kt++) {
        As[lcol + 0][lrow] = a_pre.x;
        As[lcol + 1][lrow] = a_pre.y;
        As[lcol + 2][lrow] = a_pre.z;
        As[lcol + 3][lrow] = a_pre.w;
        Bs[lcol + 0][lrow] = b_pre.x;
        Bs[lcol + 1][lrow] = b_pre.y;
        Bs[lcol + 2][lrow] = b_pre.z;
        Bs[lcol + 3][lrow] = b_pre.w;
        __syncthreads();
        if (kt + 1 < HIDC / 8) {
            a_pre = *(const float4*)(Ap + (kt + 1) * 8);
            b_pre = *(const float4*)(Bp + (kt + 1) * 8);
        }
#pragma unroll
        for (int k = 0; k < 8; k++) {
            float a[8], b[8];
            *(float4*)(a)     = *(const float4*)(&As[k][ty * 8]);
            *(float4*)(a + 4) = *(const float4*)(&As[k][ty * 8 + 4]);
            *(float4*)(b)     = *(const float4*)(&Bs[k][tx * 8]);
            *(float4*)(b + 4) = *(const float4*)(&Bs[k][tx * 8 + 4]);
#pragma unroll
            for (int i = 0; i < 8; i++)
#pragma unroll
                for (int j = 0; j < 8; j++)
                    acc[i][j] += a[i] * b[j];
        }
        __syncthreads();
    }

#pragma unroll
    for (int i = 0; i < 8; i++) {
        const int row = m0 + ty * 8 + i;
        float* crow = C + (size_t)row * HIDC + n0 + tx * 8;
        const float* brow = bias + n0 + tx * 8;
        float out[8];
#pragma unroll
        for (int j = 0; j < 8; j++) out[j] = acc[i][j] + brow[j];
        if (resid != nullptr) {
            const float* rrow = resid + (size_t)row * HIDC + n0 + tx * 8;
#pragma unroll
            for (int j = 0; j < 8; j++) out[j] += rrow[j];
        }
        *(float4*)(crow)     = *(float4*)(out);
        *(float4*)(crow + 4) = *(float4*)(out + 4);
    }
}

__global__ __launch_bounds__(256, 2) void qkv_gemm(const float* __restrict__ H,
    const float* __restrict__ Wq, const float* __restrict__ bq,
    const float* __restrict__ Wk, const float* __restrict__ bk,
    const float* __restrict__ Wv, const float* __restrict__ bv)
{
    const float* W;
    const float* bias;
    float* out;
    if (blockIdx.z == 0)      { W = Wq; bias = bq; out = g_q; }
    else if (blockIdx.z == 1) { W = Wk; bias = bk; out = g_k; }
    else                      { W = Wv; bias = bv; out = g_v; }
    gemm_body(H, W, bias, nullptr, out);
}

__global__ __launch_bounds__(256, 2) void o_gemm(const float* __restrict__ Wo,
    const float* __restrict__ bo, const float* __restrict__ H)
{
    // g_x = ctx @ Wo^T + bo + hidden  (residual fused into epilogue)
    gemm_body(g_ctx, Wo, bo, H, g_x);
}

// ---------------------------------------------------------------------------
// Fused attention: per-(b, h, 32 q-rows) block.
//   scores = (Q K^T + bias)/sqrt(32); softmax; probs -> d_out; ctx = P V
// smem: scores [32][1025], K/V chunk [256][36], bias strip [1056]
// ---------------------------------------------------------------------------
constexpr int SC_STRIDE = 1025;
constexpr int KV_STRIDE = 36;
constexpr int SMEM_FLOATS = 32 * SC_STRIDE + 256 * KV_STRIDE + 1056;  // 43072
constexpr size_t ATTN_SMEM_BYTES = (size_t)SMEM_FLOATS * sizeof(float);

__global__ __launch_bounds__(256, 1) void attn_kernel(const float* __restrict__ dist_emb,
                                                      float* __restrict__ probs_out)
{
    extern __shared__ float sm[];
    float* sc = sm;                          // [32][1025]
    float* kv = sm + 32 * SC_STRIDE;         // [256][36]
    float* bs = kv + 256 * KV_STRIDE;        // [1055]

    const int t  = threadIdx.x;
    const int q0 = blockIdx.x * 32;
    const int h  = blockIdx.y;
    const int b  = blockIdx.z;

    const size_t bh_off = (size_t)b * SEQ * HIDC + (size_t)h * HDC;
    const float* Qb = g_q + bh_off;   // row stride HIDC
    const float* Kb = g_k + bh_off;
    const float* Vb = g_v + bh_off;

    // bias strip: rel = (q0+qi) - k + 1023 -> r = qi - k + 1023 in [0,1054]
    // bs[r] = dist_emb[(q0 + r)*HD + h]
    for (int r = t; r < 1055; r += 256)
        bs[r] = dist_emb[(size_t)(q0 + r) * HDC + h];

    const int qi = t >> 3;            // 0..31 : this thread's q row
    const int lk = t & 7;
    const int c4 = lk * 4;

    // load this thread's q row into registers
    float qreg[32];
    {
        const float* qrow = Qb + (size_t)(q0 + qi) * HIDC;
#pragma unroll
        for (int d4 = 0; d4 < 8; d4++) {
            float4 v = *(const float4*)(qrow + 4 * d4);
            qreg[4 * d4 + 0] = v.x; qreg[4 * d4 + 1] = v.y;
            qreg[4 * d4 + 2] = v.z; qreg[4 * d4 + 3] = v.w;
        }
    }

    const float scale = 0.17677669529663688f;  // 1/sqrt(32)

    // ---- Phase 1: scores ----
    for (int c = 0; c < 4; c++) {
        __syncthreads();
#pragma unroll
        for (int p = 0; p < 8; p++) {
            int row = p * 32 + qi;
            float4 v = *(const float4*)(Kb + (size_t)(c * 256 + row) * HIDC + c4);
            *(float4*)(kv + row * KV_STRIDE + c4) = v;
        }
        __syncthreads();
#pragma unroll 4
        for (int j = 0; j < 32; j++) {
            int kj = lk + 8 * j;
            const float* kr = kv + kj * KV_STRIDE;
            float acc = 0.f;
#pragma unroll
            for (int d4 = 0; d4 < 8; d4++) {
                float4 kf = *(const float4*)(kr + 4 * d4);
                acc += qreg[4 * d4 + 0] * kf.x;
                acc += qreg[4 * d4 + 1] * kf.y;
                acc += qreg[4 * d4 + 2] * kf.z;
                acc += qreg[4 * d4 + 3] * kf.w;
            }
            int kg = c * 256 + kj;
            sc[qi * SC_STRIDE + kg] = (acc + bs[qi - kg + 1023]) * scale;
        }
    }
    __syncthreads();

    // ---- Phase 2: softmax + write probs ----
    {
        const int w = t >> 5, lane = t & 31;
        float* pb = probs_out + ((size_t)(b * NHC + h) * SEQ + q0) * SEQ;
        for (int rr = 0; rr < 4; rr++) {
            int r = w + 8 * rr;
            float* row = sc + r * SC_STRIDE;
            float mx = -1e30f;
            for (int i = lane; i < 1024; i += 32) mx = fmaxf(mx, row[i]);
#pragma unroll
            for (int o = 16; o > 0; o >>= 1)
                mx = fmaxf(mx, __shfl_xor_sync(0xffffffffu, mx, o));
            float sum = 0.f;
            for (int i = lane; i < 1024; i += 32) {
                float e = __expf(row[i] - mx);
                row[i] = e;
                sum += e;
            }
#pragma unroll
            for (int o = 16; o > 0; o >>= 1)
                sum += __shfl_xor_sync(0xffffffffu, sum, o);
            float inv = 1.f / sum;
            float* pr = pb + (size_t)r * SEQ;
            for (int i = lane; i < 1024; i += 32) {
                float p = row[i] * inv;
                row[i] = p;
                pr[i]  = p;
            }
        }
    }
    __syncthreads();

    // ---- Phase 3: ctx = P @ V ----
    float a0 = 0.f, a1 = 0.f, a2 = 0.f, a3 = 0.f;
    for (int c = 0; c < 4; c++) {
        __syncthreads();
#pragma unroll
        for (int p = 0; p < 8; p++) {
            int row = p * 32 + qi;
            float4 v = *(const float4*)(Vb + (size_t)(c * 256 + row) * HIDC + c4);
            *(float4*)(kv + row * KV_STRIDE + c4) = v;
        }
        __syncthreads();
        const float* prow = sc + qi * SC_STRIDE + c * 256;
#pragma unroll 8
        for (int kk = 0; kk < 256; kk++) {
            float p = prow[kk];
            float4 v = *(const float4*)(kv + kk * KV_STRIDE + c4);
            a0 += p * v.x; a1 += p * v.y; a2 += p * v.z; a3 += p * v.w;
        }
    }
    *(float4*)(g_ctx + (size_t)(b * SEQ + q0 + qi) * HIDC + h * HDC + c4) =
        make_float4(a0, a1, a2, a3);
}

// ---------------------------------------------------------------------------
// Residual is already in g_x; exact two-pass LayerNorm.
// ---------------------------------------------------------------------------
__global__ void ln_kernel(const float* __restrict__ gamma,
                          const float* __restrict__ beta,
                          float* __restrict__ out)
{
    __shared__ float red[8];
    const int row = blockIdx.x, t = threadIdx.x;
    const int w = t >> 5, lane = t & 31;

    float4 v = *((const float4*)(g_x + (size_t)row * HIDC) + t);
    float s = v.x + v.y + v.z + v.w;
#pragma unroll
    for (int o = 16; o > 0; o >>= 1) s += __shfl_xor_sync(0xffffffffu, s, o);
    if (lane == 0) red[w] = s;
    __syncthreads();
    if (t == 0) {
        float tt = 0.f;
#pragma unroll
        for (int i = 0; i < 8; i++) tt += red[i];
        red[0] = tt;
    }
    __syncthreads();
    const float mu = red[0] * (1.f / 1024.f);
    __syncthreads();

    float dx = v.x - mu, dy = v.y - mu, dz = v.z - mu, dw = v.w - mu;
    float sq = dx * dx + dy * dy + dz * dz + dw * dw;
#pragma unroll
    for (int o = 16; o > 0; o >>= 1) sq += __shfl_xor_sync(0xffffffffu, sq, o);
    if (lane == 0) red[w] = sq;
    __syncthreads();
    if (t == 0) {
        float tt = 0.f;
#pragma unroll
        for (int i = 0; i < 8; i++) tt += red[i];
        red[0] = tt;
    }
    __syncthreads();
    const float inv = rsqrtf(red[0] * (1.f / 1024.f) + 1e-12f);

    float4 g  = *((const float4*)gamma + t);
    float4 bt = *((const float4*)beta + t);
    float4 o4;
    o4.x = dx * inv * g.x + bt.x;
    o4.y = dy * inv * g.y + bt.y;
    o4.z = dz * inv * g.z + bt.z;
    o4.w = dw * inv * g.w + bt.w;
    *((float4*)(out + (size_t)row * HIDC) + t) = o4;
}

// ---------------------------------------------------------------------------
// Launch. Inputs (metadata order):
// 0 hidden_states, 1 Wq, 2 bq, 3 Wk, 4 bk, 5 Wv, 6 bv, 7 Wo, 8 bo,
// 9 ln_gamma, 10 ln_beta, 11 dist_emb
// Output: [out (4*1024*1024) | probs (4*32*1024*1024)] fp32
// ---------------------------------------------------------------------------
extern "C" void kernel_launch(void* const* d_in, const int* in_sizes, int n_in,
                              void* d_out, int out_size)
{
    (void)in_sizes; (void)n_in; (void)out_size;
    const float* hidden = (const float*)d_in[0];
    const float* Wq = (const float*)d_in[1];
    const float* bq = (const float*)d_in[2];
    const float* Wk = (const float*)d_in[3];
    const float* bk = (const float*)d_in[4];
    const float* Wv = (const float*)d_in[5];
    const float* bv = (const float*)d_in[6];
    const float* Wo = (const float*)d_in[7];
    const float* bo = (const float*)d_in[8];
    const float* gamma = (const float*)d_in[9];
    const float* beta  = (const float*)d_in[10];
    const float* dist  = (const float*)d_in[11];

    float* out   = (float*)d_out;
    float* probs = out + (size_t)BATCH * SEQ * HIDC;

    cudaFuncSetAttribute(attn_kernel, cudaFuncAttributeMaxDynamicSharedMemorySize,
                         (int)ATTN_SMEM_BYTES);

    qkv_gemm<<<dim3(8, 32, 3), 256>>>(hidden, Wq, bq, Wk, bk, Wv, bv);
    attn_kernel<<<dim3(32, 32, 4), 256, ATTN_SMEM_BYTES>>>(dist, probs);
    o_gemm<<<dim3(8, 32, 1), 256>>>(Wo, bo, hidden);
    ln_kernel<<<MR, 256>>>(gamma, beta, out);
}

// round 4
// speedup vs baseline: 1.1176x; 1.1176x over previous
#include <cuda_runtime.h>
#include <cstdint>
#include <cstddef>

// Problem constants
constexpr int SEQ   = 1024;
constexpr int HIDC  = 1024;
constexpr int NHC   = 32;
constexpr int HDC   = 32;
constexpr int BATCH = 4;
constexpr int MR    = BATCH * SEQ;   // 4096 rows

// Scratch
__device__ float g_q[(size_t)MR * HIDC];
__device__ float g_k[(size_t)MR * HIDC];
__device__ float g_v[(size_t)MR * HIDC];
__device__ float g_ctx[(size_t)MR * HIDC];
__device__ float g_x[(size_t)MR * HIDC];

// ---------------------------------------------------------------------------
// 3xTF32 tensor-core GEMM: C[m][n] = sum_k A[m][k]*B[n][k] + bias[n] (+resid)
// A: (4096 x 1024) row-major, B: (1024 x 1024) row-major (torch Linear weight
// layout == the "col-major B" the m16n8k8.row.col mma wants).
// CTA tile 128x128x16, 8 warps (2 M x 4 N), warp tile 64x32.
// ---------------------------------------------------------------------------
constexpr int LDT = 20;  // padded smem k-stride (floats): conflict-free frags

__device__ __forceinline__ uint32_t f2tf32(float x) {
    uint32_t r;
    asm("cvt.rna.tf32.f32 %0, %1;" : "=r"(r) : "f"(x));
    return r;
}

__device__ __forceinline__ void mma_tf32(float* c, const uint32_t* a, const uint32_t* b) {
    asm volatile(
        "mma.sync.aligned.m16n8k8.row.col.f32.tf32.tf32.f32 "
        "{%0,%1,%2,%3}, {%4,%5,%6,%7}, {%8,%9}, {%0,%1,%2,%3};\n"
        : "+f"(c[0]), "+f"(c[1]), "+f"(c[2]), "+f"(c[3])
        : "r"(a[0]), "r"(a[1]), "r"(a[2]), "r"(a[3]), "r"(b[0]), "r"(b[1]));
}

__device__ __forceinline__ void cvt_store8(uint32_t* sh, uint32_t* sl,
                                           int row, int col, float4 v0, float4 v1) {
    // store 8 floats (cols col..col+3 and col+4..col+7 would be wrong; v0 at col, v1 at col+... )
    uint32_t h0[4], l0[4];
    h0[0] = f2tf32(v0.x); l0[0] = f2tf32(v0.x - __uint_as_float(h0[0]));
    h0[1] = f2tf32(v0.y); l0[1] = f2tf32(v0.y - __uint_as_float(h0[1]));
    h0[2] = f2tf32(v0.z); l0[2] = f2tf32(v0.z - __uint_as_float(h0[2]));
    h0[3] = f2tf32(v0.w); l0[3] = f2tf32(v0.w - __uint_as_float(h0[3]));
    *(uint4*)&sh[row * LDT + col] = *(uint4*)h0;
    *(uint4*)&sl[row * LDT + col] = *(uint4*)l0;
    uint32_t h1[4], l1[4];
    h1[0] = f2tf32(v1.x); l1[0] = f2tf32(v1.x - __uint_as_float(h1[0]));
    h1[1] = f2tf32(v1.y); l1[1] = f2tf32(v1.y - __uint_as_float(h1[1]));
    h1[2] = f2tf32(v1.z); l1[2] = f2tf32(v1.z - __uint_as_float(h1[2]));
    h1[3] = f2tf32(v1.w); l1[3] = f2tf32(v1.w - __uint_as_float(h1[3]));
    *(uint4*)&sh[row * LDT + col + 4] = *(uint4*)h1;
    *(uint4*)&sl[row * LDT + col + 4] = *(uint4*)l1;
}

__device__ __forceinline__ void gemm_tc_body(const float* __restrict__ A,
                                             const float* __restrict__ B,
                                             const float* __restrict__ bias,
                                             const float* __restrict__ resid,
                                             float* __restrict__ C)
{
    __shared__ uint32_t sAh[128 * LDT], sAl[128 * LDT];
    __shared__ uint32_t sBh[128 * LDT], sBl[128 * LDT];

    const int t    = threadIdx.x;
    const int m0   = blockIdx.y * 128;
    const int n0   = blockIdx.x * 128;
    const int wid  = t >> 5, lane = t & 31;
    const int wm   = wid & 1, wn = wid >> 1;   // warps: 2 in M x 4 in N
    const int g    = lane >> 2, t4 = lane & 3;

    // gmem tile-load mapping: each thread loads 2 rows x 4 floats per matrix
    const int lr = t >> 2;             // 0..63
    const int lq = (t & 3) * 4;        // 0,4,8,12
    const float* Ap = A + (size_t)(m0 + lr) * HIDC + lq;
    const float* Bp = B + (size_t)(n0 + lr) * HIDC + lq;

    float acc[4][4][4];
#pragma unroll
    for (int i = 0; i < 4; i++)
#pragma unroll
        for (int j = 0; j < 4; j++)
#pragma unroll
            for (int r = 0; r < 4; r++) acc[i][j][r] = 0.f;

    float4 ra0 = *(const float4*)(Ap);
    float4 ra1 = *(const float4*)(Ap + (size_t)64 * HIDC);
    float4 rb0 = *(const float4*)(Bp);
    float4 rb1 = *(const float4*)(Bp + (size_t)64 * HIDC);

    for (int kt = 0; kt < HIDC / 16; kt++) {
        __syncthreads();
        // convert to tf32 hi/lo and stage in smem (4 floats at col lq per row)
        {
            uint32_t h[4], l[4];
            h[0] = f2tf32(ra0.x); l[0] = f2tf32(ra0.x - __uint_as_float(h[0]));
            h[1] = f2tf32(ra0.y); l[1] = f2tf32(ra0.y - __uint_as_float(h[1]));
            h[2] = f2tf32(ra0.z); l[2] = f2tf32(ra0.z - __uint_as_float(h[2]));
            h[3] = f2tf32(ra0.w); l[3] = f2tf32(ra0.w - __uint_as_float(h[3]));
            *(uint4*)&sAh[lr * LDT + lq] = *(uint4*)h;
            *(uint4*)&sAl[lr * LDT + lq] = *(uint4*)l;
            h[0] = f2tf32(ra1.x); l[0] = f2tf32(ra1.x - __uint_as_float(h[0]));
            h[1] = f2tf32(ra1.y); l[1] = f2tf32(ra1.y - __uint_as_float(h[1]));
            h[2] = f2tf32(ra1.z); l[2] = f2tf32(ra1.z - __uint_as_float(h[2]));
            h[3] = f2tf32(ra1.w); l[3] = f2tf32(ra1.w - __uint_as_float(h[3]));
            *(uint4*)&sAh[(lr + 64) * LDT + lq] = *(uint4*)h;
            *(uint4*)&sAl[(lr + 64) * LDT + lq] = *(uint4*)l;
            h[0] = f2tf32(rb0.x); l[0] = f2tf32(rb0.x - __uint_as_float(h[0]));
            h[1] = f2tf32(rb0.y); l[1] = f2tf32(rb0.y - __uint_as_float(h[1]));
            h[2] = f2tf32(rb0.z); l[2] = f2tf32(rb0.z - __uint_as_float(h[2]));
            h[3] = f2tf32(rb0.w); l[3] = f2tf32(rb0.w - __uint_as_float(h[3]));
            *(uint4*)&sBh[lr * LDT + lq] = *(uint4*)h;
            *(uint4*)&sBl[lr * LDT + lq] = *(uint4*)l;
            h[0] = f2tf32(rb1.x); l[0] = f2tf32(rb1.x - __uint_as_float(h[0]));
            h[1] = f2tf32(rb1.y); l[1] = f2tf32(rb1.y - __uint_as_float(h[1]));
            h[2] = f2tf32(rb1.z); l[2] = f2tf32(rb1.z - __uint_as_float(h[2]));
            h[3] = f2tf32(rb1.w); l[3] = f2tf32(rb1.w - __uint_as_float(h[3]));
            *(uint4*)&sBh[(lr + 64) * LDT + lq] = *(uint4*)h;
            *(uint4*)&sBl[(lr + 64) * LDT + lq] = *(uint4*)l;
        }
        __syncthreads();

        if (kt + 1 < HIDC / 16) {
            const float* Ap2 = Ap + (kt + 1) * 16;
            const float* Bp2 = Bp + (kt + 1) * 16;
            ra0 = *(const float4*)(Ap2);
            ra1 = *(const float4*)(Ap2 + (size_t)64 * HIDC);
            rb0 = *(const float4*)(Bp2);
            rb1 = *(const float4*)(Bp2 + (size_t)64 * HIDC);
        }

#pragma unroll
        for (int ks = 0; ks < 2; ks++) {
            const int kb = ks * 8 + t4;
            uint32_t bh[4][2], bl[4][2];
#pragma unroll
            for (int nf = 0; nf < 4; nf++) {
                const int n = (wn * 32 + nf * 8 + g) * LDT;
                bh[nf][0] = sBh[n + kb];
                bh[nf][1] = sBh[n + kb + 4];
                bl[nf][0] = sBl[n + kb];
                bl[nf][1] = sBl[n + kb + 4];
            }
#pragma unroll
            for (int mf = 0; mf < 4; mf++) {
                const int m = (wm * 64 + mf * 16 + g) * LDT;
                uint32_t ah[4], al[4];
                ah[0] = sAh[m + kb];
                ah[1] = sAh[m + 8 * LDT + kb];
                ah[2] = sAh[m + kb + 4];
                ah[3] = sAh[m + 8 * LDT + kb + 4];
                al[0] = sAl[m + kb];
                al[1] = sAl[m + 8 * LDT + kb];
                al[2] = sAl[m + kb + 4];
                al[3] = sAl[m + 8 * LDT + kb + 4];
#pragma unroll
                for (int nf = 0; nf < 4; nf++) {
                    mma_tf32(acc[mf][nf], ah, bh[nf]);  // hi*hi
                    mma_tf32(acc[mf][nf], ah, bl[nf]);  // hi*lo
                    mma_tf32(acc[mf][nf], al, bh[nf]);  // lo*hi
                }
            }
        }
    }

    // Epilogue: C fragment layout m16n8: c0 (g, 2*t4) c1 (g, 2*t4+1)
    //                                   c2 (g+8, 2*t4) c3 (g+8, 2*t4+1)
#pragma unroll
    for (int mf = 0; mf < 4; mf++) {
#pragma unroll
        for (int nf = 0; nf < 4; nf++) {
            const int row = m0 + wm * 64 + mf * 16 + g;
            const int col = n0 + wn * 32 + nf * 8 + t4 * 2;
            float2 bb = *(const float2*)(bias + col);
            float2 o0, o1;
            o0.x = acc[mf][nf][0] + bb.x;
            o0.y = acc[mf][nf][1] + bb.y;
            o1.x = acc[mf][nf][2] + bb.x;
            o1.y = acc[mf][nf][3] + bb.y;
            if (resid != nullptr) {
                float2 r0 = *(const float2*)(resid + (size_t)row * HIDC + col);
                float2 r1 = *(const float2*)(resid + (size_t)(row + 8) * HIDC + col);
                o0.x += r0.x; o0.y += r0.y;
                o1.x += r1.x; o1.y += r1.y;
            }
            *(float2*)(C + (size_t)row * HIDC + col)       = o0;
            *(float2*)(C + (size_t)(row + 8) * HIDC + col) = o1;
        }
    }
}

__global__ __launch_bounds__(256, 2) void qkv_gemm(const float* __restrict__ H,
    const float* __restrict__ Wq, const float* __restrict__ bq,
    const float* __restrict__ Wk, const float* __restrict__ bk,
    const float* __restrict__ Wv, const float* __restrict__ bv)
{
    const float* W;
    const float* bias;
    float* out;
    if (blockIdx.z == 0)      { W = Wq; bias = bq; out = g_q; }
    else if (blockIdx.z == 1) { W = Wk; bias = bk; out = g_k; }
    else                      { W = Wv; bias = bv; out = g_v; }
    gemm_tc_body(H, W, bias, nullptr, out);
}

__global__ __launch_bounds__(256, 2) void o_gemm(const float* __restrict__ Wo,
    const float* __restrict__ bo, const float* __restrict__ H)
{
    gemm_tc_body(g_ctx, Wo, bo, H, g_x);
}

// ---------------------------------------------------------------------------
// Fused attention (unchanged from R3): per-(b, h, 32 q-rows) block.
// ---------------------------------------------------------------------------
constexpr int SC_STRIDE = 1025;
constexpr int KV_STRIDE = 36;
constexpr int SMEM_FLOATS = 32 * SC_STRIDE + 256 * KV_STRIDE + 1056;
constexpr size_t ATTN_SMEM_BYTES = (size_t)SMEM_FLOATS * sizeof(float);

__global__ __launch_bounds__(256, 1) void attn_kernel(const float* __restrict__ dist_emb,
                                                      float* __restrict__ probs_out)
{
    extern __shared__ float sm[];
    float* sc = sm;
    float* kv = sm + 32 * SC_STRIDE;
    float* bs = kv + 256 * KV_STRIDE;

    const int t  = threadIdx.x;
    const int q0 = blockIdx.x * 32;
    const int h  = blockIdx.y;
    const int b  = blockIdx.z;

    const size_t bh_off = (size_t)b * SEQ * HIDC + (size_t)h * HDC;
    const float* Qb = g_q + bh_off;
    const float* Kb = g_k + bh_off;
    const float* Vb = g_v + bh_off;

    for (int r = t; r < 1055; r += 256)
        bs[r] = dist_emb[(size_t)(q0 + r) * HDC + h];

    const int qi = t >> 3;
    const int lk = t & 7;
    const int c4 = lk * 4;

    float qreg[32];
    {
        const float* qrow = Qb + (size_t)(q0 + qi) * HIDC;
#pragma unroll
        for (int d4 = 0; d4 < 8; d4++) {
            float4 v = *(const float4*)(qrow + 4 * d4);
            qreg[4 * d4 + 0] = v.x; qreg[4 * d4 + 1] = v.y;
            qreg[4 * d4 + 2] = v.z; qreg[4 * d4 + 3] = v.w;
        }
    }

    const float scale = 0.17677669529663688f;

    for (int c = 0; c < 4; c++) {
        __syncthreads();
#pragma unroll
        for (int p = 0; p < 8; p++) {
            int row = p * 32 + qi;
            float4 v = *(const float4*)(Kb + (size_t)(c * 256 + row) * HIDC + c4);
            *(float4*)(kv + row * KV_STRIDE + c4) = v;
        }
        __syncthreads();
#pragma unroll 4
        for (int j = 0; j < 32; j++) {
            int kj = lk + 8 * j;
            const float* kr = kv + kj * KV_STRIDE;
            float acc = 0.f;
#pragma unroll
            for (int d4 = 0; d4 < 8; d4++) {
                float4 kf = *(const float4*)(kr + 4 * d4);
                acc += qreg[4 * d4 + 0] * kf.x;
                acc += qreg[4 * d4 + 1] * kf.y;
                acc += qreg[4 * d4 + 2] * kf.z;
                acc += qreg[4 * d4 + 3] * kf.w;
            }
            int kg = c * 256 + kj;
            sc[qi * SC_STRIDE + kg] = (acc + bs[qi - kg + 1023]) * scale;
        }
    }
    __syncthreads();

    {
        const int w = t >> 5, lane = t & 31;
        float* pb = probs_out + ((size_t)(b * NHC + h) * SEQ + q0) * SEQ;
        for (int rr = 0; rr < 4; rr++) {
            int r = w + 8 * rr;
            float* row = sc + r * SC_STRIDE;
            float mx = -1e30f;
            for (int i = lane; i < 1024; i += 32) mx = fmaxf(mx, row[i]);
#pragma unroll
            for (int o = 16; o > 0; o >>= 1)
                mx = fmaxf(mx, __shfl_xor_sync(0xffffffffu, mx, o));
            float sum = 0.f;
            for (int i = lane; i < 1024; i += 32) {
                float e = __expf(row[i] - mx);
                row[i] = e;
                sum += e;
            }
#pragma unroll
            for (int o = 16; o > 0; o >>= 1)
                sum += __shfl_xor_sync(0xffffffffu, sum, o);
            float inv = 1.f / sum;
            float* pr = pb + (size_t)r * SEQ;
            for (int i = lane; i < 1024; i += 32) {
                float p = row[i] * inv;
                row[i] = p;
                pr[i]  = p;
            }
        }
    }
    __syncthreads();

    float a0 = 0.f, a1 = 0.f, a2 = 0.f, a3 = 0.f;
    for (int c = 0; c < 4; c++) {
        __syncthreads();
#pragma unroll
        for (int p = 0; p < 8; p++) {
            int row = p * 32 + qi;
            float4 v = *(const float4*)(Vb + (size_t)(c * 256 + row) * HIDC + c4);
            *(float4*)(kv + row * KV_STRIDE + c4) = v;
        }
        __syncthreads();
        const float* prow = sc + qi * SC_STRIDE + c * 256;
#pragma unroll 8
        for (int kk = 0; kk < 256; kk++) {
            float p = prow[kk];
            float4 v = *(const float4*)(kv + kk * KV_STRIDE + c4);
            a0 += p * v.x; a1 += p * v.y; a2 += p * v.z; a3 += p * v.w;
        }
    }
    *(float4*)(g_ctx + (size_t)(b * SEQ + q0 + qi) * HIDC + h * HDC + c4) =
        make_float4(a0, a1, a2, a3);
}

// ---------------------------------------------------------------------------
// LayerNorm (unchanged)
// ---------------------------------------------------------------------------
__global__ void ln_kernel(const float* __restrict__ gamma,
                          const float* __restrict__ beta,
                          float* __restrict__ out)
{
    __shared__ float red[8];
    const int row = blockIdx.x, t = threadIdx.x;
    const int w = t >> 5, lane = t & 31;

    float4 v = *((const float4*)(g_x + (size_t)row * HIDC) + t);
    float s = v.x + v.y + v.z + v.w;
#pragma unroll
    for (int o = 16; o > 0; o >>= 1) s += __shfl_xor_sync(0xffffffffu, s, o);
    if (lane == 0) red[w] = s;
    __syncthreads();
    if (t == 0) {
        float tt = 0.f;
#pragma unroll
        for (int i = 0; i < 8; i++) tt += red[i];
        red[0] = tt;
    }
    __syncthreads();
    const float mu = red[0] * (1.f / 1024.f);
    __syncthreads();

    float dx = v.x - mu, dy = v.y - mu, dz = v.z - mu, dw = v.w - mu;
    float sq = dx * dx + dy * dy + dz * dz + dw * dw;
#pragma unroll
    for (int o = 16; o > 0; o >>= 1) sq += __shfl_xor_sync(0xffffffffu, sq, o);
    if (lane == 0) red[w] = sq;
    __syncthreads();
    if (t == 0) {
        float tt = 0.f;
#pragma unroll
        for (int i = 0; i < 8; i++) tt += red[i];
        red[0] = tt;
    }
    __syncthreads();
    const float inv = rsqrtf(red[0] * (1.f / 1024.f) + 1e-12f);

    float4 g  = *((const float4*)gamma + t);
    float4 bt = *((const float4*)beta + t);
    float4 o4;
    o4.x = dx * inv * g.x + bt.x;
    o4.y = dy * inv * g.y + bt.y;
    o4.z = dz * inv * g.z + bt.z;
    o4.w = dw * inv * g.w + bt.w;
    *((float4*)(out + (size_t)row * HIDC) + t) = o4;
}

// ---------------------------------------------------------------------------
// Launch
// ---------------------------------------------------------------------------
extern "C" void kernel_launch(void* const* d_in, const int* in_sizes, int n_in,
                              void* d_out, int out_size)
{
    (void)in_sizes; (void)n_in; (void)out_size;
    const float* hidden = (const float*)d_in[0];
    const float* Wq = (const float*)d_in[1];
    const float* bq = (const float*)d_in[2];
    const float* Wk = (const float*)d_in[3];
    const float* bk = (const float*)d_in[4];
    const float* Wv = (const float*)d_in[5];
    const float* bv = (const float*)d_in[6];
    const float* Wo = (const float*)d_in[7];
    const float* bo = (const float*)d_in[8];
    const float* gamma = (const float*)d_in[9];
    const float* beta  = (const float*)d_in[10];
    const float* dist  = (const float*)d_in[11];

    float* out   = (float*)d_out;
    float* probs = out + (size_t)BATCH * SEQ * HIDC;

    cudaFuncSetAttribute(attn_kernel, cudaFuncAttributeMaxDynamicSharedMemorySize,
                         (int)ATTN_SMEM_BYTES);

    qkv_gemm<<<dim3(8, 32, 3), 256>>>(hidden, Wq, bq, Wk, bk, Wv, bv);
    attn_kernel<<<dim3(32, 32, 4), 256, ATTN_SMEM_BYTES>>>(dist, probs);
    o_gemm<<<dim3(8, 32, 1), 256>>>(Wo, bo, hidden);
    ln_kernel<<<MR, 256>>>(gamma, beta, out);
}

// round 5
// speedup vs baseline: 1.1183x; 1.0006x over previous
#include <cuda_runtime.h>
#include <cstdint>
#include <cstddef>

// Problem constants
constexpr int SEQ   = 1024;
constexpr int HIDC  = 1024;
constexpr int NHC   = 32;
constexpr int HDC   = 32;
constexpr int BATCH = 4;
constexpr int MR    = BATCH * SEQ;   // 4096 rows

// Scratch
__device__ float g_q[(size_t)MR * HIDC];
__device__ float g_k[(size_t)MR * HIDC];
__device__ float g_v[(size_t)MR * HIDC];
__device__ float g_ctx[(size_t)MR * HIDC];
__device__ float g_x[(size_t)MR * HIDC];

// ---------------------------------------------------------------------------
// 3xTF32 tensor-core GEMM: C[m][n] = sum_k A[m][k]*B[n][k] + bias[n] (+resid)
// A: (4096 x 1024) row-major, B: (1024 x 1024) row-major (torch Linear weight
// layout == the "col-major B" the m16n8k8.row.col mma wants).
// CTA tile 128x128x16, 8 warps (2 M x 4 N), warp tile 64x32.
// ---------------------------------------------------------------------------
constexpr int LDT = 20;  // padded smem k-stride (floats): conflict-free frags

__device__ __forceinline__ uint32_t f2tf32(float x) {
    uint32_t r;
    asm("cvt.rna.tf32.f32 %0, %1;" : "=r"(r) : "f"(x));
    return r;
}

__device__ __forceinline__ void mma_tf32(float* c, const uint32_t* a, const uint32_t* b) {
    asm volatile(
        "mma.sync.aligned.m16n8k8.row.col.f32.tf32.tf32.f32 "
        "{%0,%1,%2,%3}, {%4,%5,%6,%7}, {%8,%9}, {%0,%1,%2,%3};\n"
        : "+f"(c[0]), "+f"(c[1]), "+f"(c[2]), "+f"(c[3])
        : "r"(a[0]), "r"(a[1]), "r"(a[2]), "r"(a[3]), "r"(b[0]), "r"(b[1]));
}

__device__ __forceinline__ void cvt_store8(uint32_t* sh, uint32_t* sl,
                                           int row, int col, float4 v0, float4 v1) {
    // store 8 floats (cols col..col+3 and col+4..col+7 would be wrong; v0 at col, v1 at col+... )
    uint32_t h0[4], l0[4];
    h0[0] = f2tf32(v0.x); l0[0] = f2tf32(v0.x - __uint_as_float(h0[0]));
    h0[1] = f2tf32(v0.y); l0[1] = f2tf32(v0.y - __uint_as_float(h0[1]));
    h0[2] = f2tf32(v0.z); l0[2] = f2tf32(v0.z - __uint_as_float(h0[2]));
    h0[3] = f2tf32(v0.w); l0[3] = f2tf32(v0.w - __uint_as_float(h0[3]));
    *(uint4*)&sh[row * LDT + col] = *(uint4*)h0;
    *(uint4*)&sl[row * LDT + col] = *(uint4*)l0;
    uint32_t h1[4], l1[4];
    h1[0] = f2tf32(v1.x); l1[0] = f2tf32(v1.x - __uint_as_float(h1[0]));
    h1[1] = f2tf32(v1.y); l1[1] = f2tf32(v1.y - __uint_as_float(h1[1]));
    h1[2] = f2tf32(v1.z); l1[2] = f2tf32(v1.z - __uint_as_float(h1[2]));
    h1[3] = f2tf32(v1.w); l1[3] = f2tf32(v1.w - __uint_as_float(h1[3]));
    *(uint4*)&sh[row * LDT + col + 4] = *(uint4*)h1;
    *(uint4*)&sl[row * LDT + col + 4] = *(uint4*)l1;
}

__device__ __forceinline__ void gemm_tc_body(const float* __restrict__ A,
                                             const float* __restrict__ B,
                                             const float* __restrict__ bias,
                                             const float* __restrict__ resid,
                                             float* __restrict__ C)
{
    __shared__ uint32_t sAh[128 * LDT], sAl[128 * LDT];
    __shared__ uint32_t sBh[128 * LDT], sBl[128 * LDT];

    const int t    = threadIdx.x;
    const int m0   = blockIdx.y * 128;
    const int n0   = blockIdx.x * 128;
    const int wid  = t >> 5, lane = t & 31;
    const int wm   = wid & 1, wn = wid >> 1;   // warps: 2 in M x 4 in N
    const int g    = lane >> 2, t4 = lane & 3;

    // gmem tile-load mapping: each thread loads 2 rows x 4 floats per matrix
    const int lr = t >> 2;             // 0..63
    const int lq = (t & 3) * 4;        // 0,4,8,12
    const float* Ap = A + (size_t)(m0 + lr) * HIDC + lq;
    const float* Bp = B + (size_t)(n0 + lr) * HIDC + lq;

    float acc[4][4][4];
#pragma unroll
    for (int i = 0; i < 4; i++)
#pragma unroll
        for (int j = 0; j < 4; j++)
#pragma unroll
            for (int r = 0; r < 4; r++) acc[i][j][r] = 0.f;

    float4 ra0 = *(const float4*)(Ap);
    float4 ra1 = *(const float4*)(Ap + (size_t)64 * HIDC);
    float4 rb0 = *(const float4*)(Bp);
    float4 rb1 = *(const float4*)(Bp + (size_t)64 * HIDC);

    for (int kt = 0; kt < HIDC / 16; kt++) {
        __syncthreads();
        // convert to tf32 hi/lo and stage in smem (4 floats at col lq per row)
        {
            uint32_t h[4], l[4];
            h[0] = f2tf32(ra0.x); l[0] = f2tf32(ra0.x - __uint_as_float(h[0]));
            h[1] = f2tf32(ra0.y); l[1] = f2tf32(ra0.y - __uint_as_float(h[1]));
            h[2] = f2tf32(ra0.z); l[2] = f2tf32(ra0.z - __uint_as_float(h[2]));
            h[3] = f2tf32(ra0.w); l[3] = f2tf32(ra0.w - __uint_as_float(h[3]));
            *(uint4*)&sAh[lr * LDT + lq] = *(uint4*)h;
            *(uint4*)&sAl[lr * LDT + lq] = *(uint4*)l;
            h[0] = f2tf32(ra1.x); l[0] = f2tf32(ra1.x - __uint_as_float(h[0]));
            h[1] = f2tf32(ra1.y); l[1] = f2tf32(ra1.y - __uint_as_float(h[1]));
            h[2] = f2tf32(ra1.z); l[2] = f2tf32(ra1.z - __uint_as_float(h[2]));
            h[3] = f2tf32(ra1.w); l[3] = f2tf32(ra1.w - __uint_as_float(h[3]));
            *(uint4*)&sAh[(lr + 64) * LDT + lq] = *(uint4*)h;
            *(uint4*)&sAl[(lr + 64) * LDT + lq] = *(uint4*)l;
            h[0] = f2tf32(rb0.x); l[0] = f2tf32(rb0.x - __uint_as_float(h[0]));
            h[1] = f2tf32(rb0.y); l[1] = f2tf32(rb0.y - __uint_as_float(h[1]));
            h[2] = f2tf32(rb0.z); l[2] = f2tf32(rb0.z - __uint_as_float(h[2]));
            h[3] = f2tf32(rb0.w); l[3] = f2tf32(rb0.w - __uint_as_float(h[3]));
            *(uint4*)&sBh[lr * LDT + lq] = *(uint4*)h;
            *(uint4*)&sBl[lr * LDT + lq] = *(uint4*)l;
            h[0] = f2tf32(rb1.x); l[0] = f2tf32(rb1.x - __uint_as_float(h[0]));
            h[1] = f2tf32(rb1.y); l[1] = f2tf32(rb1.y - __uint_as_float(h[1]));
            h[2] = f2tf32(rb1.z); l[2] = f2tf32(rb1.z - __uint_as_float(h[2]));
            h[3] = f2tf32(rb1.w); l[3] = f2tf32(rb1.w - __uint_as_float(h[3]));
            *(uint4*)&sBh[(lr + 64) * LDT + lq] = *(uint4*)h;
            *(uint4*)&sBl[(lr + 64) * LDT + lq] = *(uint4*)l;
        }
        __syncthreads();

        if (kt + 1 < HIDC / 16) {
            const float* Ap2 = Ap + (kt + 1) * 16;
            const float* Bp2 = Bp + (kt + 1) * 16;
            ra0 = *(const float4*)(Ap2);
            ra1 = *(const float4*)(Ap2 + (size_t)64 * HIDC);
            rb0 = *(const float4*)(Bp2);
            rb1 = *(const float4*)(Bp2 + (size_t)64 * HIDC);
        }

#pragma unroll
        for (int ks = 0; ks < 2; ks++) {
            const int kb = ks * 8 + t4;
            uint32_t bh[4][2], bl[4][2];
#pragma unroll
            for (int nf = 0; nf < 4; nf++) {
                const int n = (wn * 32 + nf * 8 + g) * LDT;
                bh[nf][0] = sBh[n + kb];
                bh[nf][1] = sBh[n + kb + 4];
                bl[nf][0] = sBl[n + kb];
                bl[nf][1] = sBl[n + kb + 4];
            }
#pragma unroll
            for (int mf = 0; mf < 4; mf++) {
                const int m = (wm * 64 + mf * 16 + g) * LDT;
                uint32_t ah[4], al[4];
                ah[0] = sAh[m + kb];
                ah[1] = sAh[m + 8 * LDT + kb];
                ah[2] = sAh[m + kb + 4];
                ah[3] = sAh[m + 8 * LDT + kb + 4];
                al[0] = sAl[m + kb];
                al[1] = sAl[m + 8 * LDT + kb];
                al[2] = sAl[m + kb + 4];
                al[3] = sAl[m + 8 * LDT + kb + 4];
#pragma unroll
                for (int nf = 0; nf < 4; nf++) {
                    mma_tf32(acc[mf][nf], ah, bh[nf]);  // hi*hi
                    mma_tf32(acc[mf][nf], ah, bl[nf]);  // hi*lo
                    mma_tf32(acc[mf][nf], al, bh[nf]);  // lo*hi
                }
            }
        }
    }

    // Epilogue: C fragment layout m16n8: c0 (g, 2*t4) c1 (g, 2*t4+1)
    //                                   c2 (g+8, 2*t4) c3 (g+8, 2*t4+1)
#pragma unroll
    for (int mf = 0; mf < 4; mf++) {
#pragma unroll
        for (int nf = 0; nf < 4; nf++) {
            const int row = m0 + wm * 64 + mf * 16 + g;
            const int col = n0 + wn * 32 + nf * 8 + t4 * 2;
            float2 bb = *(const float2*)(bias + col);
            float2 o0, o1;
            o0.x = acc[mf][nf][0] + bb.x;
            o0.y = acc[mf][nf][1] + bb.y;
            o1.x = acc[mf][nf][2] + bb.x;
            o1.y = acc[mf][nf][3] + bb.y;
            if (resid != nullptr) {
                float2 r0 = *(const float2*)(resid + (size_t)row * HIDC + col);
                float2 r1 = *(const float2*)(resid + (size_t)(row + 8) * HIDC + col);
                o0.x += r0.x; o0.y += r0.y;
                o1.x += r1.x; o1.y += r1.y;
            }
            *(float2*)(C + (size_t)row * HIDC + col)       = o0;
            *(float2*)(C + (size_t)(row + 8) * HIDC + col) = o1;
        }
    }
}

__global__ __launch_bounds__(256, 2) void qkv_gemm(const float* __restrict__ H,
    const float* __restrict__ Wq, const float* __restrict__ bq,
    const float* __restrict__ Wk, const float* __restrict__ bk,
    const float* __restrict__ Wv, const float* __restrict__ bv)
{
    const float* W;
    const float* bias;
    float* out;
    if (blockIdx.z == 0)      { W = Wq; bias = bq; out = g_q; }
    else if (blockIdx.z == 1) { W = Wk; bias = bk; out = g_k; }
    else                      { W = Wv; bias = bv; out = g_v; }
    gemm_tc_body(H, W, bias, nullptr, out);
}

__global__ __launch_bounds__(256, 2) void o_gemm(const float* __restrict__ Wo,
    const float* __restrict__ bo, const float* __restrict__ H)
{
    gemm_tc_body(g_ctx, Wo, bo, H, g_x);
}

// ---------------------------------------------------------------------------
// Fused attention (unchanged from R3): per-(b, h, 32 q-rows) block.
// ---------------------------------------------------------------------------
constexpr int SC_STRIDE = 1025;
constexpr int KV_STRIDE = 36;
constexpr int SMEM_FLOATS = 32 * SC_STRIDE + 256 * KV_STRIDE + 1056;
constexpr size_t ATTN_SMEM_BYTES = (size_t)SMEM_FLOATS * sizeof(float);

__global__ __launch_bounds__(256, 1) void attn_kernel(const float* __restrict__ dist_emb,
                                                      float* __restrict__ probs_out)
{
    extern __shared__ float sm[];
    float* sc = sm;
    float* kv = sm + 32 * SC_STRIDE;
    float* bs = kv + 256 * KV_STRIDE;

    const int t  = threadIdx.x;
    const int q0 = blockIdx.x * 32;
    const int h  = blockIdx.y;
    const int b  = blockIdx.z;

    const size_t bh_off = (size_t)b * SEQ * HIDC + (size_t)h * HDC;
    const float* Qb = g_q + bh_off;
    const float* Kb = g_k + bh_off;
    const float* Vb = g_v + bh_off;

    for (int r = t; r < 1055; r += 256)
        bs[r] = dist_emb[(size_t)(q0 + r) * HDC + h];

    const int qi = t >> 3;
    const int lk = t & 7;
    const int c4 = lk * 4;

    float qreg[32];
    {
        const float* qrow = Qb + (size_t)(q0 + qi) * HIDC;
#pragma unroll
        for (int d4 = 0; d4 < 8; d4++) {
            float4 v = *(const float4*)(qrow + 4 * d4);
            qreg[4 * d4 + 0] = v.x; qreg[4 * d4 + 1] = v.y;
            qreg[4 * d4 + 2] = v.z; qreg[4 * d4 + 3] = v.w;
        }
    }

    const float scale = 0.17677669529663688f;

    for (int c = 0; c < 4; c++) {
        __syncthreads();
#pragma unroll
        for (int p = 0; p < 8; p++) {
            int row = p * 32 + qi;
            float4 v = *(const float4*)(Kb + (size_t)(c * 256 + row) * HIDC + c4);
            *(float4*)(kv + row * KV_STRIDE + c4) = v;
        }
        __syncthreads();
#pragma unroll 4
        for (int j = 0; j < 32; j++) {
            int kj = lk + 8 * j;
            const float* kr = kv + kj * KV_STRIDE;
            float acc = 0.f;
#pragma unroll
            for (int d4 = 0; d4 < 8; d4++) {
                float4 kf = *(const float4*)(kr + 4 * d4);
                acc += qreg[4 * d4 + 0] * kf.x;
                acc += qreg[4 * d4 + 1] * kf.y;
                acc += qreg[4 * d4 + 2] * kf.z;
                acc += qreg[4 * d4 + 3] * kf.w;
            }
            int kg = c * 256 + kj;
            sc[qi * SC_STRIDE + kg] = (acc + bs[qi - kg + 1023]) * scale;
        }
    }
    __syncthreads();

    {
        const int w = t >> 5, lane = t & 31;
        float* pb = probs_out + ((size_t)(b * NHC + h) * SEQ + q0) * SEQ;
        for (int rr = 0; rr < 4; rr++) {
            int r = w + 8 * rr;
            float* row = sc + r * SC_STRIDE;
            float mx = -1e30f;
            for (int i = lane; i < 1024; i += 32) mx = fmaxf(mx, row[i]);
#pragma unroll
            for (int o = 16; o > 0; o >>= 1)
                mx = fmaxf(mx, __shfl_xor_sync(0xffffffffu, mx, o));
            float sum = 0.f;
            for (int i = lane; i < 1024; i += 32) {
                float e = __expf(row[i] - mx);
                row[i] = e;
                sum += e;
            }
#pragma unroll
            for (int o = 16; o > 0; o >>= 1)
                sum += __shfl_xor_sync(0xffffffffu, sum, o);
            float inv = 1.f / sum;
            float* pr = pb + (size_t)r * SEQ;
            for (int i = lane; i < 1024; i += 32) {
                float p = row[i] * inv;
                row[i] = p;
                pr[i]  = p;
            }
        }
    }
    __syncthreads();

    float a0 = 0.f, a1 = 0.f, a2 = 0.f, a3 = 0.f;
    for (int c = 0; c < 4; c++) {
        __syncthreads();
#pragma unroll
        for (int p = 0; p < 8; p++) {
            int row = p * 32 + qi;
            float4 v = *(const float4*)(Vb + (size_t)(c * 256 + row) * HIDC + c4);
            *(float4*)(kv + row * KV_STRIDE + c4) = v;
        }
        __syncthreads();
        const float* prow = sc + qi * SC_STRIDE + c * 256;
#pragma unroll 8
        for (int kk = 0; kk < 256; kk++) {
            float p = prow[kk];
            float4 v = *(const float4*)(kv + kk * KV_STRIDE + c4);
            a0 += p * v.x; a1 += p * v.y; a2 += p * v.z; a3 += p * v.w;
        }
    }
    *(float4*)(g_ctx + (size_t)(b * SEQ + q0 + qi) * HIDC + h * HDC + c4) =
        make_float4(a0, a1, a2, a3);
}

// ---------------------------------------------------------------------------
// LayerNorm (unchanged)
// ---------------------------------------------------------------------------
__global__ void ln_kernel(const float* __restrict__ gamma,
                          const float* __restrict__ beta,
                          float* __restrict__ out)
{
    __shared__ float red[8];
    const int row = blockIdx.x, t = threadIdx.x;
    const int w = t >> 5, lane = t & 31;

    float4 v = *((const float4*)(g_x + (size_t)row * HIDC) + t);
    float s = v.x + v.y + v.z + v.w;
#pragma unroll
    for (int o = 16; o > 0; o >>= 1) s += __shfl_xor_sync(0xffffffffu, s, o);
    if (lane == 0) red[w] = s;
    __syncthreads();
    if (t == 0) {
        float tt = 0.f;
#pragma unroll
        for (int i = 0; i < 8; i++) tt += red[i];
        red[0] = tt;
    }
    __syncthreads();
    const float mu = red[0] * (1.f / 1024.f);
    __syncthreads();

    float dx = v.x - mu, dy = v.y - mu, dz = v.z - mu, dw = v.w - mu;
    float sq = dx * dx + dy * dy + dz * dz + dw * dw;
#pragma unroll
    for (int o = 16; o > 0; o >>= 1) sq += __shfl_xor_sync(0xffffffffu, sq, o);
    if (lane == 0) red[w] = sq;
    __syncthreads();
    if (t == 0) {
        float tt = 0.f;
#pragma unroll
        for (int i = 0; i < 8; i++) tt += red[i];
        red[0] = tt;
    }
    __syncthreads();
    const float inv = rsqrtf(red[0] * (1.f / 1024.f) + 1e-12f);

    float4 g  = *((const float4*)gamma + t);
    float4 bt = *((const float4*)beta + t);
    float4 o4;
    o4.x = dx * inv * g.x + bt.x;
    o4.y = dy * inv * g.y + bt.y;
    o4.z = dz * inv * g.z + bt.z;
    o4.w = dw * inv * g.w + bt.w;
    *((float4*)(out + (size_t)row * HIDC) + t) = o4;
}

// ---------------------------------------------------------------------------
// Launch
// ---------------------------------------------------------------------------
extern "C" void kernel_launch(void* const* d_in, const int* in_sizes, int n_in,
                              void* d_out, int out_size)
{
    (void)in_sizes; (void)n_in; (void)out_size;
    const float* hidden = (const float*)d_in[0];
    const float* Wq = (const float*)d_in[1];
    const float* bq = (const float*)d_in[2];
    const float* Wk = (const float*)d_in[3];
    const float* bk = (const float*)d_in[4];
    const float* Wv = (const float*)d_in[5];
    const float* bv = (const float*)d_in[6];
    const float* Wo = (const float*)d_in[7];
    const float* bo = (const float*)d_in[8];
    const float* gamma = (const float*)d_in[9];
    const float* beta  = (const float*)d_in[10];
    const float* dist  = (const float*)d_in[11];

    float* out   = (float*)d_out;
    float* probs = out + (size_t)BATCH * SEQ * HIDC;

    cudaFuncSetAttribute(attn_kernel, cudaFuncAttributeMaxDynamicSharedMemorySize,
                         (int)ATTN_SMEM_BYTES);

    qkv_gemm<<<dim3(8, 32, 3), 256>>>(hidden, Wq, bq, Wk, bk, Wv, bv);
    attn_kernel<<<dim3(32, 32, 4), 256, ATTN_SMEM_BYTES>>>(dist, probs);
    o_gemm<<<dim3(8, 32, 1), 256>>>(Wo, bo, hidden);
    ln_kernel<<<MR, 256>>>(gamma, beta, out);
}

// round 6
// speedup vs baseline: 1.5532x; 1.3889x over previous
#include <cuda_runtime.h>
#include <cstdint>
#include <cstddef>

// Problem constants
constexpr int SEQ   = 1024;
constexpr int HIDC  = 1024;
constexpr int NHC   = 32;
constexpr int HDC   = 32;
constexpr int BATCH = 4;
constexpr int MR    = BATCH * SEQ;   // 4096 rows

// Scratch
__device__ float g_q[(size_t)MR * HIDC];
__device__ float g_k[(size_t)MR * HIDC];
__device__ float g_v[(size_t)MR * HIDC];
__device__ float g_ctx[(size_t)MR * HIDC];
__device__ float g_x[(size_t)MR * HIDC];

__device__ __forceinline__ uint32_t f2tf32(float x) {
    uint32_t r;
    asm("cvt.rna.tf32.f32 %0, %1;" : "=r"(r) : "f"(x));
    return r;
}

__device__ __forceinline__ void mma_tf32(float* c, const uint32_t* a, const uint32_t* b) {
    asm volatile(
        "mma.sync.aligned.m16n8k8.row.col.f32.tf32.tf32.f32 "
        "{%0,%1,%2,%3}, {%4,%5,%6,%7}, {%8,%9}, {%0,%1,%2,%3};\n"
        : "+f"(c[0]), "+f"(c[1]), "+f"(c[2]), "+f"(c[3])
        : "r"(a[0]), "r"(a[1]), "r"(a[2]), "r"(a[3]), "r"(b[0]), "r"(b[1]));
}

// ---------------------------------------------------------------------------
// 3xTF32 tensor-core GEMM (unchanged from R5): C = A @ B^T + bias (+resid)
// ---------------------------------------------------------------------------
constexpr int LDT = 20;

__device__ __forceinline__ void gemm_tc_body(const float* __restrict__ A,
                                             const float* __restrict__ B,
                                             const float* __restrict__ bias,
                                             const float* __restrict__ resid,
                                             float* __restrict__ C)
{
    __shared__ uint32_t sAh[128 * LDT], sAl[128 * LDT];
    __shared__ uint32_t sBh[128 * LDT], sBl[128 * LDT];

    const int t    = threadIdx.x;
    const int m0   = blockIdx.y * 128;
    const int n0   = blockIdx.x * 128;
    const int wid  = t >> 5, lane = t & 31;
    const int wm   = wid & 1, wn = wid >> 1;
    const int g    = lane >> 2, t4 = lane & 3;

    const int lr = t >> 2;
    const int lq = (t & 3) * 4;
    const float* Ap = A + (size_t)(m0 + lr) * HIDC + lq;
    const float* Bp = B + (size_t)(n0 + lr) * HIDC + lq;

    float acc[4][4][4];
#pragma unroll
    for (int i = 0; i < 4; i++)
#pragma unroll
        for (int j = 0; j < 4; j++)
#pragma unroll
            for (int r = 0; r < 4; r++) acc[i][j][r] = 0.f;

    float4 ra0 = *(const float4*)(Ap);
    float4 ra1 = *(const float4*)(Ap + (size_t)64 * HIDC);
    float4 rb0 = *(const float4*)(Bp);
    float4 rb1 = *(const float4*)(Bp + (size_t)64 * HIDC);

    for (int kt = 0; kt < HIDC / 16; kt++) {
        __syncthreads();
        {
            uint32_t h[4], l[4];
            h[0] = f2tf32(ra0.x); l[0] = f2tf32(ra0.x - __uint_as_float(h[0]));
            h[1] = f2tf32(ra0.y); l[1] = f2tf32(ra0.y - __uint_as_float(h[1]));
            h[2] = f2tf32(ra0.z); l[2] = f2tf32(ra0.z - __uint_as_float(h[2]));
            h[3] = f2tf32(ra0.w); l[3] = f2tf32(ra0.w - __uint_as_float(h[3]));
            *(uint4*)&sAh[lr * LDT + lq] = *(uint4*)h;
            *(uint4*)&sAl[lr * LDT + lq] = *(uint4*)l;
            h[0] = f2tf32(ra1.x); l[0] = f2tf32(ra1.x - __uint_as_float(h[0]));
            h[1] = f2tf32(ra1.y); l[1] = f2tf32(ra1.y - __uint_as_float(h[1]));
            h[2] = f2tf32(ra1.z); l[2] = f2tf32(ra1.z - __uint_as_float(h[2]));
            h[3] = f2tf32(ra1.w); l[3] = f2tf32(ra1.w - __uint_as_float(h[3]));
            *(uint4*)&sAh[(lr + 64) * LDT + lq] = *(uint4*)h;
            *(uint4*)&sAl[(lr + 64) * LDT + lq] = *(uint4*)l;
            h[0] = f2tf32(rb0.x); l[0] = f2tf32(rb0.x - __uint_as_float(h[0]));
            h[1] = f2tf32(rb0.y); l[1] = f2tf32(rb0.y - __uint_as_float(h[1]));
            h[2] = f2tf32(rb0.z); l[2] = f2tf32(rb0.z - __uint_as_float(h[2]));
            h[3] = f2tf32(rb0.w); l[3] = f2tf32(rb0.w - __uint_as_float(h[3]));
            *(uint4*)&sBh[lr * LDT + lq] = *(uint4*)h;
            *(uint4*)&sBl[lr * LDT + lq] = *(uint4*)l;
            h[0] = f2tf32(rb1.x); l[0] = f2tf32(rb1.x - __uint_as_float(h[0]));
            h[1] = f2tf32(rb1.y); l[1] = f2tf32(rb1.y - __uint_as_float(h[1]));
            h[2] = f2tf32(rb1.z); l[2] = f2tf32(rb1.z - __uint_as_float(h[2]));
            h[3] = f2tf32(rb1.w); l[3] = f2tf32(rb1.w - __uint_as_float(h[3]));
            *(uint4*)&sBh[(lr + 64) * LDT + lq] = *(uint4*)h;
            *(uint4*)&sBl[(lr + 64) * LDT + lq] = *(uint4*)l;
        }
        __syncthreads();

        if (kt + 1 < HIDC / 16) {
            const float* Ap2 = Ap + (kt + 1) * 16;
            const float* Bp2 = Bp + (kt + 1) * 16;
            ra0 = *(const float4*)(Ap2);
            ra1 = *(const float4*)(Ap2 + (size_t)64 * HIDC);
            rb0 = *(const float4*)(Bp2);
            rb1 = *(const float4*)(Bp2 + (size_t)64 * HIDC);
        }

#pragma unroll
        for (int ks = 0; ks < 2; ks++) {
            const int kb = ks * 8 + t4;
            uint32_t bh[4][2], bl[4][2];
#pragma unroll
            for (int nf = 0; nf < 4; nf++) {
                const int n = (wn * 32 + nf * 8 + g) * LDT;
                bh[nf][0] = sBh[n + kb];
                bh[nf][1] = sBh[n + kb + 4];
                bl[nf][0] = sBl[n + kb];
                bl[nf][1] = sBl[n + kb + 4];
            }
#pragma unroll
            for (int mf = 0; mf < 4; mf++) {
                const int m = (wm * 64 + mf * 16 + g) * LDT;
                uint32_t ah[4], al[4];
                ah[0] = sAh[m + kb];
                ah[1] = sAh[m + 8 * LDT + kb];
                ah[2] = sAh[m + kb + 4];
                ah[3] = sAh[m + 8 * LDT + kb + 4];
                al[0] = sAl[m + kb];
                al[1] = sAl[m + 8 * LDT + kb];
                al[2] = sAl[m + kb + 4];
                al[3] = sAl[m + 8 * LDT + kb + 4];
#pragma unroll
                for (int nf = 0; nf < 4; nf++) {
                    mma_tf32(acc[mf][nf], ah, bh[nf]);
                    mma_tf32(acc[mf][nf], ah, bl[nf]);
                    mma_tf32(acc[mf][nf], al, bh[nf]);
                }
            }
        }
    }

#pragma unroll
    for (int mf = 0; mf < 4; mf++) {
#pragma unroll
        for (int nf = 0; nf < 4; nf++) {
            const int row = m0 + wm * 64 + mf * 16 + g;
            const int col = n0 + wn * 32 + nf * 8 + t4 * 2;
            float2 bb = *(const float2*)(bias + col);
            float2 o0, o1;
            o0.x = acc[mf][nf][0] + bb.x;
            o0.y = acc[mf][nf][1] + bb.y;
            o1.x = acc[mf][nf][2] + bb.x;
            o1.y = acc[mf][nf][3] + bb.y;
            if (resid != nullptr) {
                float2 r0 = *(const float2*)(resid + (size_t)row * HIDC + col);
                float2 r1 = *(const float2*)(resid + (size_t)(row + 8) * HIDC + col);
                o0.x += r0.x; o0.y += r0.y;
                o1.x += r1.x; o1.y += r1.y;
            }
            *(float2*)(C + (size_t)row * HIDC + col)       = o0;
            *(float2*)(C + (size_t)(row + 8) * HIDC + col) = o1;
        }
    }
}

__global__ __launch_bounds__(256, 2) void qkv_gemm(const float* __restrict__ H,
    const float* __restrict__ Wq, const float* __restrict__ bq,
    const float* __restrict__ Wk, const float* __restrict__ bk,
    const float* __restrict__ Wv, const float* __restrict__ bv)
{
    const float* W;
    const float* bias;
    float* out;
    if (blockIdx.z == 0)      { W = Wq; bias = bq; out = g_q; }
    else if (blockIdx.z == 1) { W = Wk; bias = bk; out = g_k; }
    else                      { W = Wv; bias = bv; out = g_v; }
    gemm_tc_body(H, W, bias, nullptr, out);
}

__global__ __launch_bounds__(256, 2) void o_gemm(const float* __restrict__ Wo,
    const float* __restrict__ bo, const float* __restrict__ H)
{
    gemm_tc_body(g_ctx, Wo, bo, H, g_x);
}

// ---------------------------------------------------------------------------
// Tensor-core fused attention. Per block: (b, h, 32 q-rows).
//  Phase 1: S = (Q K^T + bias)/sqrt(32) via 3xTF32 mma, S in smem (32x1024)
//  Phase 2: exact softmax; write probs to gmem; normalized P back to S
//  Phase 3: ctx^T = V^T P^T via 3xTF32 mma (roles swapped so V stages like K)
// ---------------------------------------------------------------------------
constexpr int SST = 1032;   // S smem row stride
constexpr int KST = 33;     // K/V/Q smem row stride (tf32 words)

constexpr int OFF_S  = 0;                 // 32*1032 = 33024 floats
constexpr int OFF_KH = 33024;             // 256*33  = 8448
constexpr int OFF_KL = OFF_KH + 8448;     // 8448
constexpr int OFF_QH = OFF_KL + 8448;     // 32*33 = 1056
constexpr int OFF_QL = OFF_QH + 1056;     // 1056
constexpr int OFF_BS = OFF_QL + 1056;     // 1056
constexpr int ATTN_FLOATS = OFF_BS + 1056;  // 53088
constexpr size_t ATTN_SMEM_BYTES = (size_t)ATTN_FLOATS * sizeof(float);

__global__ __launch_bounds__(256, 1) void attn_kernel(const float* __restrict__ dist_emb,
                                                      float* __restrict__ probs_out)
{
    extern __shared__ float sm[];
    float*    S  = sm + OFF_S;
    uint32_t* kh = (uint32_t*)(sm + OFF_KH);
    uint32_t* kl = (uint32_t*)(sm + OFF_KL);
    uint32_t* qh = (uint32_t*)(sm + OFF_QH);
    uint32_t* ql = (uint32_t*)(sm + OFF_QL);
    float*    bs = sm + OFF_BS;

    const int t   = threadIdx.x;
    const int q0  = blockIdx.x * 32;
    const int h   = blockIdx.y;
    const int b   = blockIdx.z;
    const int wid = t >> 5, lane = t & 31;
    const int g   = lane >> 2, t4 = lane & 3;

    const size_t bh_off = (size_t)b * SEQ * HIDC + (size_t)h * HDC;
    const float* Qb = g_q + bh_off;
    const float* Kb = g_k + bh_off;
    const float* Vb = g_v + bh_off;

    // bias strip: bs[r] = dist_emb[(q0 + r)*HD + h], r in [0,1054]
    for (int r = t; r < 1055; r += 256)
        bs[r] = dist_emb[(size_t)(q0 + r) * HDC + h];

    // stage Q tile (32x32) as tf32 hi/lo
    {
        const int row = t >> 3, c4 = (t & 7) * 4;
        float4 v = *(const float4*)(Qb + (size_t)(q0 + row) * HIDC + c4);
        float vv[4] = {v.x, v.y, v.z, v.w};
#pragma unroll
        for (int j = 0; j < 4; j++) {
            uint32_t hi = f2tf32(vv[j]);
            qh[row * KST + c4 + j] = hi;
            ql[row * KST + c4 + j] = f2tf32(vv[j] - __uint_as_float(hi));
        }
    }
    __syncthreads();

    // preload Q A-fragments (reused for every key chunk)
    uint32_t qfh[2][4][4], qfl[2][4][4];
#pragma unroll
    for (int mf = 0; mf < 2; mf++)
#pragma unroll
        for (int ks = 0; ks < 4; ks++) {
            const int r0 = (mf * 16 + g) * KST;
            const int r1 = r0 + 8 * KST;
            const int k0 = ks * 8 + t4;
            qfh[mf][ks][0] = qh[r0 + k0];
            qfh[mf][ks][1] = qh[r1 + k0];
            qfh[mf][ks][2] = qh[r0 + k0 + 4];
            qfh[mf][ks][3] = qh[r1 + k0 + 4];
            qfl[mf][ks][0] = ql[r0 + k0];
            qfl[mf][ks][1] = ql[r1 + k0];
            qfl[mf][ks][2] = ql[r0 + k0 + 4];
            qfl[mf][ks][3] = ql[r1 + k0 + 4];
        }

    const float scale = 0.17677669529663688f;  // 1/sqrt(32)

    // ---- Phase 1: S = (Q K^T + bias) * scale ----
    for (int c = 0; c < 4; c++) {
        __syncthreads();
        // stage K chunk (256x32) as tf32 hi/lo
#pragma unroll
        for (int p = 0; p < 8; p++) {
            const int row = p * 32 + (t >> 3), c4 = (t & 7) * 4;
            float4 v = *(const float4*)(Kb + (size_t)(c * 256 + row) * HIDC + c4);
            float vv[4] = {v.x, v.y, v.z, v.w};
#pragma unroll
            for (int j = 0; j < 4; j++) {
                uint32_t hi = f2tf32(vv[j]);
                kh[row * KST + c4 + j] = hi;
                kl[row * KST + c4 + j] = f2tf32(vv[j] - __uint_as_float(hi));
            }
        }
        __syncthreads();

        const int kw = wid * 32;   // this warp's 32 keys within chunk
#pragma unroll
        for (int nf = 0; nf < 4; nf++) {
            uint32_t bhh[4][2], bll[4][2];
#pragma unroll
            for (int ks = 0; ks < 4; ks++) {
                const int n = (kw + nf * 8 + g) * KST + ks * 8 + t4;
                bhh[ks][0] = kh[n]; bhh[ks][1] = kh[n + 4];
                bll[ks][0] = kl[n]; bll[ks][1] = kl[n + 4];
            }
#pragma unroll
            for (int mf = 0; mf < 2; mf++) {
                float acc[4] = {0.f, 0.f, 0.f, 0.f};
#pragma unroll
                for (int ks = 0; ks < 4; ks++) {
                    mma_tf32(acc, qfh[mf][ks], bhh[ks]);
                    mma_tf32(acc, qfh[mf][ks], bll[ks]);
                    mma_tf32(acc, qfl[mf][ks], bhh[ks]);
                }
                const int row0 = mf * 16 + g;
                const int row1 = row0 + 8;
                const int col  = c * 256 + kw + nf * 8 + 2 * t4;
                float2 s0, s1;
                s0.x = (acc[0] + bs[row0 - col + 1023]) * scale;
                s0.y = (acc[1] + bs[row0 - col + 1022]) * scale;
                s1.x = (acc[2] + bs[row1 - col + 1023]) * scale;
                s1.y = (acc[3] + bs[row1 - col + 1022]) * scale;
                *(float2*)&S[row0 * SST + col] = s0;
                *(float2*)&S[row1 * SST + col] = s1;
            }
        }
    }
    __syncthreads();

    // ---- Phase 2: softmax; write probs to gmem; normalized P back to S ----
    {
        float* pb = probs_out + ((size_t)(b * NHC + h) * SEQ + q0) * SEQ;
        for (int rr = 0; rr < 4; rr++) {
            const int r = wid + 8 * rr;
            float* row = S + r * SST;
            float mx = -1e30f;
            for (int i = lane; i < 1024; i += 32) mx = fmaxf(mx, row[i]);
#pragma unroll
            for (int o = 16; o > 0; o >>= 1)
                mx = fmaxf(mx, __shfl_xor_sync(0xffffffffu, mx, o));
            float sum = 0.f;
            for (int i = lane; i < 1024; i += 32) {
                float e = __expf(row[i] - mx);
                row[i] = e;
                sum += e;
            }
#pragma unroll
            for (int o = 16; o > 0; o >>= 1)
                sum += __shfl_xor_sync(0xffffffffu, sum, o);
            const float inv = 1.f / sum;
            float* pr = pb + (size_t)r * SEQ;
            for (int i = lane; i < 1024; i += 32) {
                float p = row[i] * inv;
                row[i] = p;
                pr[i]  = p;
            }
        }
    }

    // ---- Phase 3: ctx^T = V^T @ P^T (m=dim, n=q-row, k=key) ----
    float acc[2][4][4];
#pragma unroll
    for (int mf = 0; mf < 2; mf++)
#pragma unroll
        for (int nf = 0; nf < 4; nf++)
#pragma unroll
            for (int r = 0; r < 4; r++) acc[mf][nf][r] = 0.f;

    for (int c = 0; c < 4; c++) {
        __syncthreads();
        // stage V chunk (256x32) as tf32 hi/lo (same layout as K)
#pragma unroll
        for (int p = 0; p < 8; p++) {
            const int row = p * 32 + (t >> 3), c4 = (t & 7) * 4;
            float4 v = *(const float4*)(Vb + (size_t)(c * 256 + row) * HIDC + c4);
            float vv[4] = {v.x, v.y, v.z, v.w};
#pragma unroll
            for (int j = 0; j < 4; j++) {
                uint32_t hi = f2tf32(vv[j]);
                kh[row * KST + c4 + j] = hi;
                kl[row * KST + c4 + j] = f2tf32(vv[j] - __uint_as_float(hi));
            }
        }
        __syncthreads();

        const int kw = wid * 32;
#pragma unroll
        for (int ks = 0; ks < 4; ks++) {
            const int kLoc  = kw + ks * 8 + t4;      // key within chunk
            const int kGlob = c * 256 + kLoc;        // key within sequence
            // A fragments: A[m=d][k=key] = V[key][d]
            uint32_t ah[2][4], al[2][4];
#pragma unroll
            for (int mf = 0; mf < 2; mf++) {
                const int d0 = mf * 16 + g;
                const int a0 = kLoc * KST + d0;
                const int a4 = (kLoc + 4) * KST + d0;
                ah[mf][0] = kh[a0];
                ah[mf][1] = kh[a0 + 8];
                ah[mf][2] = kh[a4];
                ah[mf][3] = kh[a4 + 8];
                al[mf][0] = kl[a0];
                al[mf][1] = kl[a0 + 8];
                al[mf][2] = kl[a4];
                al[mf][3] = kl[a4 + 8];
            }
            // B fragments: B[n=q][k=key] = P[q][key], fp32 -> tf32 hi/lo
#pragma unroll
            for (int nf = 0; nf < 4; nf++) {
                const int q = nf * 8 + g;
                const float p0 = S[q * SST + kGlob];
                const float p1 = S[q * SST + kGlob + 4];
                uint32_t bh2[2], bl2[2];
                bh2[0] = f2tf32(p0); bl2[0] = f2tf32(p0 - __uint_as_float(bh2[0]));
                bh2[1] = f2tf32(p1); bl2[1] = f2tf32(p1 - __uint_as_float(bh2[1]));
#pragma unroll
                for (int mf = 0; mf < 2; mf++) {
                    mma_tf32(acc[mf][nf], ah[mf], bh2);
                    mma_tf32(acc[mf][nf], ah[mf], bl2);
                    mma_tf32(acc[mf][nf], al[mf], bh2);
                }
            }
        }
    }
    __syncthreads();

    // cross-warp reduction of partial ctx (red reuses the K hi region: 8448 fl)
    float* red = sm + OFF_KH;
#pragma unroll
    for (int mf = 0; mf < 2; mf++)
#pragma unroll
        for (int nf = 0; nf < 4; nf++) {
            const int d = mf * 16 + g;
            const int q = nf * 8 + 2 * t4;
            float* rw = red + wid * 1056;
            rw[q * 33 + d]           = acc[mf][nf][0];
            rw[(q + 1) * 33 + d]     = acc[mf][nf][1];
            rw[q * 33 + d + 8]       = acc[mf][nf][2];
            rw[(q + 1) * 33 + d + 8] = acc[mf][nf][3];
        }
    __syncthreads();

#pragma unroll
    for (int i = 0; i < 4; i++) {
        const int idx = t + i * 256;        // 0..1023
        const int q = idx >> 5, d = idx & 31;
        float s = 0.f;
#pragma unroll
        for (int w = 0; w < 8; w++) s += red[w * 1056 + q * 33 + d];
        g_ctx[(size_t)(b * SEQ + q0 + q) * HIDC + h * HDC + d] = s;
    }
}

// ---------------------------------------------------------------------------
// LayerNorm (unchanged)
// ---------------------------------------------------------------------------
__global__ void ln_kernel(const float* __restrict__ gamma,
                          const float* __restrict__ beta,
                          float* __restrict__ out)
{
    __shared__ float red[8];
    const int row = blockIdx.x, t = threadIdx.x;
    const int w = t >> 5, lane = t & 31;

    float4 v = *((const float4*)(g_x + (size_t)row * HIDC) + t);
    float s = v.x + v.y + v.z + v.w;
#pragma unroll
    for (int o = 16; o > 0; o >>= 1) s += __shfl_xor_sync(0xffffffffu, s, o);
    if (lane == 0) red[w] = s;
    __syncthreads();
    if (t == 0) {
        float tt = 0.f;
#pragma unroll
        for (int i = 0; i < 8; i++) tt += red[i];
        red[0] = tt;
    }
    __syncthreads();
    const float mu = red[0] * (1.f / 1024.f);
    __syncthreads();

    float dx = v.x - mu, dy = v.y - mu, dz = v.z - mu, dw = v.w - mu;
    float sq = dx * dx + dy * dy + dz * dz + dw * dw;
#pragma unroll
    for (int o = 16; o > 0; o >>= 1) sq += __shfl_xor_sync(0xffffffffu, sq, o);
    if (lane == 0) red[w] = sq;
    __syncthreads();
    if (t == 0) {
        float tt = 0.f;
#pragma unroll
        for (int i = 0; i < 8; i++) tt += red[i];
        red[0] = tt;
    }
    __syncthreads();
    const float inv = rsqrtf(red[0] * (1.f / 1024.f) + 1e-12f);

    float4 g  = *((const float4*)gamma + t);
    float4 bt = *((const float4*)beta + t);
    float4 o4;
    o4.x = dx * inv * g.x + bt.x;
    o4.y = dy * inv * g.y + bt.y;
    o4.z = dz * inv * g.z + bt.z;
    o4.w = dw * inv * g.w + bt.w;
    *((float4*)(out + (size_t)row * HIDC) + t) = o4;
}

// ---------------------------------------------------------------------------
// Launch
// ---------------------------------------------------------------------------
extern "C" void kernel_launch(void* const* d_in, const int* in_sizes, int n_in,
                              void* d_out, int out_size)
{
    (void)in_sizes; (void)n_in; (void)out_size;
    const float* hidden = (const float*)d_in[0];
    const float* Wq = (const float*)d_in[1];
    const float* bq = (const float*)d_in[2];
    const float* Wk = (const float*)d_in[3];
    const float* bk = (const float*)d_in[4];
    const float* Wv = (const float*)d_in[5];
    const float* bv = (const float*)d_in[6];
    const float* Wo = (const float*)d_in[7];
    const float* bo = (const float*)d_in[8];
    const float* gamma = (const float*)d_in[9];
    const float* beta  = (const float*)d_in[10];
    const float* dist  = (const float*)d_in[11];

    float* out   = (float*)d_out;
    float* probs = out + (size_t)BATCH * SEQ * HIDC;

    cudaFuncSetAttribute(attn_kernel, cudaFuncAttributeMaxDynamicSharedMemorySize,
                         (int)ATTN_SMEM_BYTES);

    qkv_gemm<<<dim3(8, 32, 3), 256>>>(hidden, Wq, bq, Wk, bk, Wv, bv);
    attn_kernel<<<dim3(32, 32, 4), 256, ATTN_SMEM_BYTES>>>(dist, probs);
    o_gemm<<<dim3(8, 32, 1), 256>>>(Wo, bo, hidden);
    ln_kernel<<<MR, 256>>>(gamma, beta, out);
}